// round 7
// baseline (speedup 1.0000x reference)
#include <cuda_runtime.h>
#include <math.h>

#define HH 512
#define WW 512
#define W2C 256
#define NC 12
#define NPIX (NC*HH*WW)
#define NSIG 6
#define MAXK 155
#define DPI 3.14159265358979323846

typedef unsigned long long u64;

__device__ float g_diff[NPIX];
__device__ ulonglong2 g_UV[NSIG][NPIX / 2];          // {U-pair, V-pair} per column-pair
__device__ float g_S[NSIG][NPIX];
__device__ float2 g_PS[NSIG][NC * (HH + 1) * W2C];   // vertical prefix of S, per column-pair
__device__ u64   g_E2[NSIG][MAXK];
__device__ u64   g_H2[NSIG][MAXK];
__device__ float g_cc[NSIG];
__device__ double g_acc[NSIG];

__constant__ int    c_k[NSIG]   = {5, 11, 21, 39, 77, 155};
__constant__ double c_sig[NSIG] = {0.6, 1.2, 2.4, 4.8, 9.6, 19.2};
__constant__ float  c_w[NSIG]   = {600.f, 500.f, 400.f, 20.f, 10.f, 10.f};

__device__ __forceinline__ u64 pk2(float lo, float hi) {
    u64 r; asm("mov.b64 %0,{%1,%2};" : "=l"(r) : "f"(lo), "f"(hi)); return r;
}
__device__ __forceinline__ void un2(u64 v, float& lo, float& hi) {
    asm("mov.b64 {%0,%1},%2;" : "=f"(lo), "=f"(hi) : "l"(v));
}
__device__ __forceinline__ u64 fma2(u64 a, u64 b, u64 c) {
    u64 d; asm("fma.rn.f32x2 %0,%1,%2,%3;" : "=l"(d) : "l"(a), "l"(b), "l"(c)); return d;
}

// ---------------------------------------------------------------------------
__global__ void init_kernel() {
    int s = blockIdx.x;
    int k = c_k[s];
    double ss = c_sig[s] * c_sig[s];
    int t = threadIdx.x;
    if (t == 0) g_acc[s] = 0.0;
    if (t < k) {
        double x = (double)t - (double)(k - 1) * 0.5;
        double e = exp(-(x * x) / (2.0 * ss));
        double h = (x * x - ss) * e / (2.0 * DPI * ss * ss);
        g_E2[s][t] = pk2((float)e, (float)e);
        g_H2[s][t] = pk2((float)h, (float)h);
    }
    __syncthreads();
    if (t == 0) {
        double sg = 0.0, sh = 0.0;
        for (int i = 0; i < k; i++) {
            float e, e1, h, h1;
            un2(g_E2[s][i], e, e1);
            un2(g_H2[s][i], h, h1);
            sg += (double)e; sh += (double)h;
        }
        g_cc[s] = (float)(2.0 * sg * sh / ((double)k * (double)k));
    }
}

// ---------------------------------------------------------------------------
__global__ void diff_kernel(const float* __restrict__ a, const float* __restrict__ b) {
    int i = blockIdx.x * blockDim.x + threadIdx.x;
    if (i < NPIX / 4) {
        float4 x = reinterpret_cast<const float4*>(a)[i];
        float4 y = reinterpret_cast<const float4*>(b)[i];
        float4 d;
        d.x = x.x - y.x; d.y = x.y - y.y; d.z = x.z - y.z; d.w = x.w - y.w;
        reinterpret_cast<float4*>(g_diff)[i] = d;
    }
}

// ---------------------------------------------------------------------------
// hpass body: horizontal convs (E, h) + box via prefix. Row-pair packed f32x2.
// Writes interleaved UV + S, per sigma.
// ---------------------------------------------------------------------------
template<int K>
__device__ __forceinline__ void hpass_body(int s, int bx, u64* smbuf) {
    constexpr int P = K / 2;
    constexpr int XW = WW + 2 * P;
    constexpr int SST = (XW + 7) / 8 + 1;
    u64* spad0 = smbuf;                 // [2][8*SST]
    u64* sE = smbuf + 2 * 8 * SST;      // [K]
    u64* sH = sE + K;                   // [K]
    int tid = threadIdx.x;
    for (int i = tid; i < K; i += 128) { sE[i] = g_E2[s][i]; sH[i] = g_H2[s][i]; }
    int r0 = bx * 4;
    for (int idx = tid; idx < 2 * XW; idx += 128) {
        int pr = (idx >= XW) ? 1 : 0;
        int x = idx - pr * XW;
        int c = x - P;
        c = c < 0 ? -c : c;
        c = c >= WW ? 2 * WW - 2 - c : c;
        const float* ra = g_diff + (size_t)(r0 + 2 * pr) * WW + c;
        spad0[pr * 8 * SST + (x & 7) * SST + (x >> 3)] = pk2(ra[0], ra[WW]);
    }
    __syncthreads();

    int tx = tid & 63;
    const u64* sp = spad0 + (tid >> 6) * 8 * SST;
    u64 w[8], AE[8], AH[8];
    float2 Sa[8];
    float Px = 0.f, Py = 0.f;
#pragma unroll
    for (int i = 0; i < 8; i++) { AE[i] = 0ull; AH[i] = 0ull; }

#pragma unroll
    for (int t = 0; t < 8; ++t) {
        u64 v = sp[t * SST + tx];
        w[t] = v;
        Sa[t].x = -Px; Sa[t].y = -Py;
        float vx, vy; un2(v, vx, vy);
        Px += vx; Py += vy;
        if (t >= K - 1) { Sa[t - K + 1].x += Px; Sa[t - K + 1].y += Py; }
    }

    constexpr int MA = (K > 9) ? ((K - 9) / 8) * 8 : 0;
    for (int m = 0; m < MA / 8; ++m) {
#pragma unroll
        for (int jj = 0; jj < 8; ++jj) {
            int d = m * 8 + jj;
            u64 e2 = sE[d], h2 = sH[d];
#pragma unroll
            for (int rr = 0; rr < 8; ++rr) {
                u64 v = w[(jj + rr) & 7];
                AE[rr] = fma2(e2, v, AE[rr]);
                AH[rr] = fma2(h2, v, AH[rr]);
            }
            u64 nv = sp[jj * SST + tx + m + 1];
            w[jj] = nv;
            float vx, vy; un2(nv, vx, vy);
            Px += vx; Py += vy;
        }
    }
#pragma unroll
    for (int e = 0; e < K - MA; ++e) {
        const int d = MA + e;
        u64 e2 = sE[d], h2 = sH[d];
#pragma unroll
        for (int rr = 0; rr < 8; ++rr) {
            u64 v = w[(d + rr) & 7];
            AE[rr] = fma2(e2, v, AE[rr]);
            AH[rr] = fma2(h2, v, AH[rr]);
        }
        if (d <= K - 2) {
            u64 nv = sp[(d & 7) * SST + tx + ((d + 8) >> 3)];
            w[d & 7] = nv;
            float vx, vy; un2(nv, vx, vy);
            Px += vx; Py += vy;
            if (d >= K - 9) { Sa[d + 9 - K].x += Px; Sa[d + 9 - K].y += Py; }
        }
    }

    // unpack rows
    float eA[8], eB[8], hA[8], hB[8];
#pragma unroll
    for (int rr = 0; rr < 8; ++rr) un2(AE[rr], eA[rr], eB[rr]);
#pragma unroll
    for (int rr = 0; rr < 8; ++rr) un2(AH[rr], hA[rr], hB[rr]);

    int rA = r0 + 2 * (tid >> 6);       // first row of this pair
    int j0 = tx * 8;                    // first column
    int c2 = j0 >> 1;                   // first column-pair index

    // interleaved UV stores: float4 = {U[2c],U[2c+1],V[2c],V[2c+1]}
    float4* UVb = (float4*)g_UV[s];
    size_t uvA = (size_t)rA * W2C + c2;
    size_t uvB = uvA + W2C;
#pragma unroll
    for (int i = 0; i < 4; ++i)
        UVb[uvA + i] = make_float4(eA[2*i], eA[2*i+1], hA[2*i], hA[2*i+1]);
#pragma unroll
    for (int i = 0; i < 4; ++i)
        UVb[uvB + i] = make_float4(eB[2*i], eB[2*i+1], hB[2*i], hB[2*i+1]);

    // S stores
    float* Sb = g_S[s];
    size_t rbase = (size_t)rA * WW + j0;
    float la[8], lb[8];
#pragma unroll
    for (int rr = 0; rr < 8; ++rr) { la[rr] = Sa[rr].x; lb[rr] = Sa[rr].y; }
    *(float4*)(Sb + rbase)          = make_float4(la[0], la[1], la[2], la[3]);
    *(float4*)(Sb + rbase + 4)      = make_float4(la[4], la[5], la[6], la[7]);
    *(float4*)(Sb + rbase + WW)     = make_float4(lb[0], lb[1], lb[2], lb[3]);
    *(float4*)(Sb + rbase + WW + 4) = make_float4(lb[4], lb[5], lb[6], lb[7]);
}

// Fat hpass: all sigmas in one launch, descending K for load balance.
__global__ void __launch_bounds__(128, 4) hpass_all() {
    __shared__ alignas(16) u64 smbuf[1672];
    int b = blockIdx.x;
    int s = b / 1536;           // 0..5 in launch order
    int bx = b - s * 1536;
    switch (s) {
        case 0: hpass_body<155>(5, bx, smbuf); break;
        case 1: hpass_body<77> (4, bx, smbuf); break;
        case 2: hpass_body<39> (3, bx, smbuf); break;
        case 3: hpass_body<21> (2, bx, smbuf); break;
        case 4: hpass_body<11> (1, bx, smbuf); break;
        default:hpass_body<5>  (0, bx, smbuf); break;
    }
}

// ---------------------------------------------------------------------------
// Column prefix sums of S (per sigma, per image): PS[r] = sum of rows [0, r).
// ---------------------------------------------------------------------------
__global__ void sprefix_all() {
    int b = blockIdx.x;                 // NSIG * NC * 2
    int s = b / (NC * 2);
    int rem = b - s * (NC * 2);
    int img = rem >> 1;
    int half = rem & 1;
    int col2 = half * 128 + threadIdx.x;
    const float2* Sq = (const float2*)g_S[s] + (size_t)img * HH * W2C;
    float2* PS = g_PS[s] + (size_t)img * (HH + 1) * W2C;
    float2 acc = make_float2(0.f, 0.f);
    PS[col2] = acc;
    for (int r = 0; r < HH; ++r) {
        float2 v = Sq[(size_t)r * W2C + col2];
        acc.x += v.x; acc.y += v.y;
        PS[(size_t)(r + 1) * W2C + col2] = acc;
    }
}

// ---------------------------------------------------------------------------
// vpass body: A = h (x) U + E (x) V vertically; box via integral image; square+reduce.
// ---------------------------------------------------------------------------
template<int K>
__device__ __forceinline__ void vpass_body(int s, int bx, int by, int bz, u64* smbuf) {
    constexpr int P = K / 2;
    u64* sE = smbuf;            // [K]
    u64* sH = sE + K;           // [K]
    float* sred = (float*)(sH + K);
    int tid = threadIdx.x;
    for (int i = tid; i < K; i += 128) { sE[i] = g_E2[s][i]; sH[i] = g_H2[s][i]; }
    __syncthreads();

    int col2 = bx * 128 + tid;
    int i0 = by * 16;
    size_t ib = (size_t)bz * (HH * W2C);
    const ulonglong2* __restrict__ UVq = (const ulonglong2*)g_UV[s] + ib;

    u64 wu[16], wv[16], A[16];
#pragma unroll
    for (int i = 0; i < 16; i++) A[i] = 0ull;
    int base = i0 - P;

#pragma unroll
    for (int t = 0; t < 16; ++t) {
        int r = base + t; r = r < 0 ? -r : r; r = r >= HH ? 2 * HH - 2 - r : r;
        ulonglong2 q = UVq[(size_t)r * W2C + col2];
        wu[t] = q.x; wv[t] = q.y;
    }

    constexpr int MA = (K > 17) ? ((K - 17) / 16) * 16 : 0;
    for (int m = 0; m < MA / 16; ++m) {
#pragma unroll
        for (int jj = 0; jj < 16; ++jj) {
            int d = m * 16 + jj;
            u64 e2 = sE[d], h2 = sH[d];
#pragma unroll
            for (int rr = 0; rr < 16; ++rr) {
                A[rr] = fma2(h2, wu[(jj + rr) & 15], A[rr]);
                A[rr] = fma2(e2, wv[(jj + rr) & 15], A[rr]);
            }
            int r = base + d + 16; r = r < 0 ? -r : r; r = r >= HH ? 2 * HH - 2 - r : r;
            ulonglong2 q = UVq[(size_t)r * W2C + col2];
            wu[jj] = q.x; wv[jj] = q.y;
        }
    }
#pragma unroll
    for (int e = 0; e < K - MA; ++e) {
        const int d = MA + e;
        u64 e2 = sE[d], h2 = sH[d];
#pragma unroll
        for (int rr = 0; rr < 16; ++rr) {
            A[rr] = fma2(h2, wu[(d + rr) & 15], A[rr]);
            A[rr] = fma2(e2, wv[(d + rr) & 15], A[rr]);
        }
        if (d <= K - 2) {
            int r = base + d + 16; r = r < 0 ? -r : r; r = r >= HH ? 2 * HH - 2 - r : r;
            ulonglong2 q = UVq[(size_t)r * W2C + col2];
            wu[d & 15] = q.x; wv[d & 15] = q.y;
        }
    }

    // box term via integral image (reflect handled in closed form)
    const float2* __restrict__ PSp = g_PS[s] + (size_t)bz * (HH + 1) * W2C;
    float2 PS1  = PSp[(size_t)1 * W2C + col2];
    float2 PSH1 = PSp[(size_t)(HH - 1) * W2C + col2];
    float cc = g_cc[s];
    float sq = 0.f;
#pragma unroll
    for (int rr = 0; rr < 16; ++rr) {
        int o = i0 + rr;
        int a = o - P, b = o + P;
        int i1 = b + 1 < HH ? b + 1 : HH;
        int i2 = a > 0 ? a : 0;
        int i3 = 1 - a > 1 ? 1 - a : 1;
        int i4t = 2 * HH - 2 - b;
        int i4 = i4t < HH - 1 ? i4t : HH - 1;
        float2 p1 = PSp[(size_t)i1 * W2C + col2];
        float2 p2 = PSp[(size_t)i2 * W2C + col2];
        float2 p3 = PSp[(size_t)i3 * W2C + col2];
        float2 p4 = PSp[(size_t)i4 * W2C + col2];
        float bxv = (p1.x - p2.x) + (p3.x - PS1.x) + (PSH1.x - p4.x);
        float byv = (p1.y - p2.y) + (p3.y - PS1.y) + (PSH1.y - p4.y);
        float ax, ay; un2(A[rr], ax, ay);
        float vx = fmaf(-cc, bxv, ax);
        float vy = fmaf(-cc, byv, ay);
        sq = fmaf(vx, vx, sq);
        sq = fmaf(vy, vy, sq);
    }
#pragma unroll
    for (int o = 16; o > 0; o >>= 1) sq += __shfl_xor_sync(0xffffffffu, sq, o);
    if ((tid & 31) == 0) sred[tid >> 5] = sq;
    __syncthreads();
    if (tid == 0)
        atomicAdd(&g_acc[s], (double)(sred[0] + sred[1] + sred[2] + sred[3]));
}

// Fat vpass: all sigmas, descending K; per sigma 768 blocks = (2, 32, 12).
__global__ void __launch_bounds__(128, 4) vpass_all() {
    __shared__ alignas(16) u64 smbuf[2 * MAXK + 4];
    int b = blockIdx.x;
    int s = b / 768;
    int id = b - s * 768;
    int bx = id & 1;
    int by = (id >> 1) & 31;
    int bz = id >> 6;
    switch (s) {
        case 0: vpass_body<155>(5, bx, by, bz, smbuf); break;
        case 1: vpass_body<77> (4, bx, by, bz, smbuf); break;
        case 2: vpass_body<39> (3, bx, by, bz, smbuf); break;
        case 3: vpass_body<21> (2, bx, by, bz, smbuf); break;
        case 4: vpass_body<11> (1, bx, by, bz, smbuf); break;
        default:vpass_body<5>  (0, bx, by, bz, smbuf); break;
    }
}

// ---------------------------------------------------------------------------
__global__ void fin_kernel(float* out) {
    double L = 0.0;
    for (int s = 0; s < NSIG; s++) L += (double)c_w[s] * g_acc[s];
    out[0] = (float)(L / (double)NPIX);
}

// ---------------------------------------------------------------------------
extern "C" void kernel_launch(void* const* d_in, const int* in_sizes, int n_in,
                              void* d_out, int out_size) {
    const float* input  = (const float*)d_in[0];
    const float* target = (const float*)d_in[1];

    init_kernel<<<NSIG, 160>>>();
    diff_kernel<<<(NPIX / 4 + 255) / 256, 256>>>(input, target);
    hpass_all<<<NSIG * 1536, 128>>>();
    sprefix_all<<<NSIG * NC * 2, 128>>>();
    vpass_all<<<NSIG * 768, 128>>>();
    fin_kernel<<<1, 1>>>((float*)d_out);
}

// round 10
// speedup vs baseline: 1.6519x; 1.6519x over previous
#include <cuda_runtime.h>
#include <math.h>

#define HH 512
#define WW 512
#define W2C 256
#define NC 12
#define NPIX (NC*HH*WW)
#define NSIG 6
#define MAXK 155
#define DPI 3.14159265358979323846

typedef unsigned long long u64;

__device__ float g_diff[NPIX];
__device__ ulonglong2 g_UV[NSIG][NPIX / 2];          // {U-pair, V-pair} per column-pair
__device__ float g_S[NSIG][NPIX];
__device__ float2 g_PS[NSIG][NC * (HH + 1) * W2C];   // vertical prefix of S, per column-pair
__device__ u64   g_E2[NSIG][MAXK];
__device__ u64   g_H2[NSIG][MAXK];
__device__ float g_cc[NSIG];
__device__ double g_acc[NSIG];

__constant__ int    c_k[NSIG]   = {5, 11, 21, 39, 77, 155};
__constant__ double c_sig[NSIG] = {0.6, 1.2, 2.4, 4.8, 9.6, 19.2};
__constant__ float  c_w[NSIG]   = {600.f, 500.f, 400.f, 20.f, 10.f, 10.f};

__device__ __forceinline__ u64 pk2(float lo, float hi) {
    u64 r; asm("mov.b64 %0,{%1,%2};" : "=l"(r) : "f"(lo), "f"(hi)); return r;
}
__device__ __forceinline__ void un2(u64 v, float& lo, float& hi) {
    asm("mov.b64 {%0,%1},%2;" : "=f"(lo), "=f"(hi) : "l"(v));
}
__device__ __forceinline__ u64 fma2(u64 a, u64 b, u64 c) {
    u64 d; asm("fma.rn.f32x2 %0,%1,%2,%3;" : "=l"(d) : "l"(a), "l"(b), "l"(c)); return d;
}

// ---------------------------------------------------------------------------
__global__ void init_kernel() {
    int s = blockIdx.x;
    int k = c_k[s];
    double ss = c_sig[s] * c_sig[s];
    int t = threadIdx.x;
    if (t == 0) g_acc[s] = 0.0;
    if (t < k) {
        double x = (double)t - (double)(k - 1) * 0.5;
        double e = exp(-(x * x) / (2.0 * ss));
        double h = (x * x - ss) * e / (2.0 * DPI * ss * ss);
        g_E2[s][t] = pk2((float)e, (float)e);
        g_H2[s][t] = pk2((float)h, (float)h);
    }
    __syncthreads();
    if (t == 0) {
        double sg = 0.0, sh = 0.0;
        for (int i = 0; i < k; i++) {
            float e, e1, h, h1;
            un2(g_E2[s][i], e, e1);
            un2(g_H2[s][i], h, h1);
            sg += (double)e; sh += (double)h;
        }
        g_cc[s] = (float)(2.0 * sg * sh / ((double)k * (double)k));
    }
}

// ---------------------------------------------------------------------------
__global__ void diff_kernel(const float* __restrict__ a, const float* __restrict__ b) {
    int i = blockIdx.x * blockDim.x + threadIdx.x;
    if (i < NPIX / 4) {
        float4 x = reinterpret_cast<const float4*>(a)[i];
        float4 y = reinterpret_cast<const float4*>(b)[i];
        float4 d;
        d.x = x.x - y.x; d.y = x.y - y.y; d.z = x.z - y.z; d.w = x.w - y.w;
        reinterpret_cast<float4*>(g_diff)[i] = d;
    }
}

// ---------------------------------------------------------------------------
// hpass body: horizontal convs (E, h) + box via prefix. Row-pair packed f32x2.
// Writes interleaved UV + S, per sigma.
// ---------------------------------------------------------------------------
template<int K>
__device__ __forceinline__ void hpass_body(int s, int bx, u64* smbuf) {
    constexpr int P = K / 2;
    constexpr int XW = WW + 2 * P;
    constexpr int SST = (XW + 7) / 8 + 1;
    u64* spad0 = smbuf;                 // [2][8*SST]
    u64* sE = smbuf + 2 * 8 * SST;      // [K]
    u64* sH = sE + K;                   // [K]
    int tid = threadIdx.x;
    for (int i = tid; i < K; i += 128) { sE[i] = g_E2[s][i]; sH[i] = g_H2[s][i]; }
    int r0 = bx * 4;
    for (int idx = tid; idx < 2 * XW; idx += 128) {
        int pr = (idx >= XW) ? 1 : 0;
        int x = idx - pr * XW;
        int c = x - P;
        c = c < 0 ? -c : c;
        c = c >= WW ? 2 * WW - 2 - c : c;
        const float* ra = g_diff + (size_t)(r0 + 2 * pr) * WW + c;
        spad0[pr * 8 * SST + (x & 7) * SST + (x >> 3)] = pk2(ra[0], ra[WW]);
    }
    __syncthreads();

    int tx = tid & 63;
    const u64* sp = spad0 + (tid >> 6) * 8 * SST;
    u64 w[8], AE[8], AH[8];
    float2 Sa[8];
    float Px = 0.f, Py = 0.f;
#pragma unroll
    for (int i = 0; i < 8; i++) { AE[i] = 0ull; AH[i] = 0ull; }

#pragma unroll
    for (int t = 0; t < 8; ++t) {
        u64 v = sp[t * SST + tx];
        w[t] = v;
        Sa[t].x = -Px; Sa[t].y = -Py;
        float vx, vy; un2(v, vx, vy);
        Px += vx; Py += vy;
        if (t >= K - 1) { Sa[t - K + 1].x += Px; Sa[t - K + 1].y += Py; }
    }

    constexpr int MA = (K > 9) ? ((K - 9) / 8) * 8 : 0;
    for (int m = 0; m < MA / 8; ++m) {
#pragma unroll
        for (int jj = 0; jj < 8; ++jj) {
            int d = m * 8 + jj;
            u64 e2 = sE[d], h2 = sH[d];
#pragma unroll
            for (int rr = 0; rr < 8; ++rr) {
                u64 v = w[(jj + rr) & 7];
                AE[rr] = fma2(e2, v, AE[rr]);
                AH[rr] = fma2(h2, v, AH[rr]);
            }
            u64 nv = sp[jj * SST + tx + m + 1];
            w[jj] = nv;
            float vx, vy; un2(nv, vx, vy);
            Px += vx; Py += vy;
        }
    }
#pragma unroll
    for (int e = 0; e < K - MA; ++e) {
        const int d = MA + e;
        u64 e2 = sE[d], h2 = sH[d];
#pragma unroll
        for (int rr = 0; rr < 8; ++rr) {
            u64 v = w[(d + rr) & 7];
            AE[rr] = fma2(e2, v, AE[rr]);
            AH[rr] = fma2(h2, v, AH[rr]);
        }
        if (d <= K - 2) {
            u64 nv = sp[(d & 7) * SST + tx + ((d + 8) >> 3)];
            w[d & 7] = nv;
            float vx, vy; un2(nv, vx, vy);
            Px += vx; Py += vy;
            if (d >= K - 9) { Sa[d + 9 - K].x += Px; Sa[d + 9 - K].y += Py; }
        }
    }

    // unpack rows
    float eA[8], eB[8], hA[8], hB[8];
#pragma unroll
    for (int rr = 0; rr < 8; ++rr) un2(AE[rr], eA[rr], eB[rr]);
#pragma unroll
    for (int rr = 0; rr < 8; ++rr) un2(AH[rr], hA[rr], hB[rr]);

    int rA = r0 + 2 * (tid >> 6);       // first row of this pair
    int j0 = tx * 8;                    // first column
    int c2 = j0 >> 1;                   // first column-pair index

    // interleaved UV stores: float4 = {U[2c],U[2c+1],V[2c],V[2c+1]}
    float4* UVb = (float4*)g_UV[s];
    size_t uvA = (size_t)rA * W2C + c2;
    size_t uvB = uvA + W2C;
#pragma unroll
    for (int i = 0; i < 4; ++i)
        UVb[uvA + i] = make_float4(eA[2*i], eA[2*i+1], hA[2*i], hA[2*i+1]);
#pragma unroll
    for (int i = 0; i < 4; ++i)
        UVb[uvB + i] = make_float4(eB[2*i], eB[2*i+1], hB[2*i], hB[2*i+1]);

    // S stores
    float* Sb = g_S[s];
    size_t rbase = (size_t)rA * WW + j0;
    float la[8], lb[8];
#pragma unroll
    for (int rr = 0; rr < 8; ++rr) { la[rr] = Sa[rr].x; lb[rr] = Sa[rr].y; }
    *(float4*)(Sb + rbase)          = make_float4(la[0], la[1], la[2], la[3]);
    *(float4*)(Sb + rbase + 4)      = make_float4(la[4], la[5], la[6], la[7]);
    *(float4*)(Sb + rbase + WW)     = make_float4(lb[0], lb[1], lb[2], lb[3]);
    *(float4*)(Sb + rbase + WW + 4) = make_float4(lb[4], lb[5], lb[6], lb[7]);
}

// Fat hpass: all sigmas in one launch, descending K for load balance.
__global__ void __launch_bounds__(128, 4) hpass_all() {
    __shared__ alignas(16) u64 smbuf[1672];
    int b = blockIdx.x;
    int s = b / 1536;           // 0..5 in launch order
    int bx = b - s * 1536;
    switch (s) {
        case 0: hpass_body<155>(5, bx, smbuf); break;
        case 1: hpass_body<77> (4, bx, smbuf); break;
        case 2: hpass_body<39> (3, bx, smbuf); break;
        case 3: hpass_body<21> (2, bx, smbuf); break;
        case 4: hpass_body<11> (1, bx, smbuf); break;
        default:hpass_body<5>  (0, bx, smbuf); break;
    }
}

// ---------------------------------------------------------------------------
// Segmented column prefix of S: PS[r] = sum of rows [0, r).
// Grid: NSIG*NC*8 chunks; block = 512 threads = 16 segments x 32 column-pairs.
// Phase A: per-thread 32-row segment sum -> shared; exclusive scan over segments;
// Phase B: re-walk segment writing PS with offset.
// ---------------------------------------------------------------------------
__global__ void __launch_bounds__(512, 2) sprefix_all() {
    __shared__ float2 ssum[16][32];
    int b = blockIdx.x;                 // NSIG * NC * 8
    int s = b / (NC * 8);
    int rem = b - s * (NC * 8);
    int img = rem >> 3;
    int chunk = rem & 7;
    int tid = threadIdx.x;
    int c = tid & 31;
    int seg = tid >> 5;                 // 0..15
    int col2 = chunk * 32 + c;
    const float2* Sq = (const float2*)g_S[s] + (size_t)img * HH * W2C + col2;
    float2* PS = g_PS[s] + (size_t)img * (HH + 1) * W2C + col2;

    int r0 = seg * 32;
    // Phase A: segment sum
    float2 acc = make_float2(0.f, 0.f);
    for (int i = 0; i < 32; ++i) {
        float2 v = Sq[(size_t)(r0 + i) * W2C];
        acc.x += v.x; acc.y += v.y;
    }
    ssum[seg][c] = acc;
    __syncthreads();
    // exclusive scan over segments for this column
    float2 off = make_float2(0.f, 0.f);
    for (int s2 = 0; s2 < 16; ++s2) {
        if (s2 < seg) { off.x += ssum[s2][c].x; off.y += ssum[s2][c].y; }
    }
    // Phase B: write PS
    for (int i = 0; i < 32; ++i) {
        PS[(size_t)(r0 + i) * W2C] = off;
        float2 v = Sq[(size_t)(r0 + i) * W2C];
        off.x += v.x; off.y += v.y;
    }
    if (seg == 15) PS[(size_t)HH * W2C] = off;
}

// ---------------------------------------------------------------------------
// vpass body: A = h (x) U + E (x) V vertically; box via integral image; square+reduce.
// ---------------------------------------------------------------------------
template<int K>
__device__ __forceinline__ void vpass_body(int s, int bx, int by, int bz, u64* smbuf) {
    constexpr int P = K / 2;
    u64* sE = smbuf;            // [K]
    u64* sH = sE + K;           // [K]
    float* sred = (float*)(sH + K);
    int tid = threadIdx.x;
    for (int i = tid; i < K; i += 128) { sE[i] = g_E2[s][i]; sH[i] = g_H2[s][i]; }
    __syncthreads();

    int col2 = bx * 128 + tid;
    int i0 = by * 16;
    size_t ib = (size_t)bz * (HH * W2C);
    const ulonglong2* __restrict__ UVq = (const ulonglong2*)g_UV[s] + ib;

    u64 wu[16], wv[16], A[16];
#pragma unroll
    for (int i = 0; i < 16; i++) A[i] = 0ull;
    int base = i0 - P;

#pragma unroll
    for (int t = 0; t < 16; ++t) {
        int r = base + t; r = r < 0 ? -r : r; r = r >= HH ? 2 * HH - 2 - r : r;
        ulonglong2 q = UVq[(size_t)r * W2C + col2];
        wu[t] = q.x; wv[t] = q.y;
    }

    constexpr int MA = (K > 17) ? ((K - 17) / 16) * 16 : 0;
    for (int m = 0; m < MA / 16; ++m) {
#pragma unroll
        for (int jj = 0; jj < 16; ++jj) {
            int d = m * 16 + jj;
            u64 e2 = sE[d], h2 = sH[d];
#pragma unroll
            for (int rr = 0; rr < 16; ++rr) {
                A[rr] = fma2(h2, wu[(jj + rr) & 15], A[rr]);
                A[rr] = fma2(e2, wv[(jj + rr) & 15], A[rr]);
            }
            int r = base + d + 16; r = r < 0 ? -r : r; r = r >= HH ? 2 * HH - 2 - r : r;
            ulonglong2 q = UVq[(size_t)r * W2C + col2];
            wu[jj] = q.x; wv[jj] = q.y;
        }
    }
#pragma unroll
    for (int e = 0; e < K - MA; ++e) {
        const int d = MA + e;
        u64 e2 = sE[d], h2 = sH[d];
#pragma unroll
        for (int rr = 0; rr < 16; ++rr) {
            A[rr] = fma2(h2, wu[(d + rr) & 15], A[rr]);
            A[rr] = fma2(e2, wv[(d + rr) & 15], A[rr]);
        }
        if (d <= K - 2) {
            int r = base + d + 16; r = r < 0 ? -r : r; r = r >= HH ? 2 * HH - 2 - r : r;
            ulonglong2 q = UVq[(size_t)r * W2C + col2];
            wu[d & 15] = q.x; wv[d & 15] = q.y;
        }
    }

    // box term via integral image (reflect handled in closed form)
    const float2* __restrict__ PSp = g_PS[s] + (size_t)bz * (HH + 1) * W2C;
    float2 PS1  = PSp[(size_t)1 * W2C + col2];
    float2 PSH1 = PSp[(size_t)(HH - 1) * W2C + col2];
    float cc = g_cc[s];
    float sq = 0.f;
#pragma unroll
    for (int rr = 0; rr < 16; ++rr) {
        int o = i0 + rr;
        int a = o - P, b = o + P;
        int i1 = b + 1 < HH ? b + 1 : HH;
        int i2 = a > 0 ? a : 0;
        int i3 = 1 - a > 1 ? 1 - a : 1;
        int i4t = 2 * HH - 2 - b;
        int i4 = i4t < HH - 1 ? i4t : HH - 1;
        float2 p1 = PSp[(size_t)i1 * W2C + col2];
        float2 p2 = PSp[(size_t)i2 * W2C + col2];
        float2 p3 = PSp[(size_t)i3 * W2C + col2];
        float2 p4 = PSp[(size_t)i4 * W2C + col2];
        float bxv = (p1.x - p2.x) + (p3.x - PS1.x) + (PSH1.x - p4.x);
        float byv = (p1.y - p2.y) + (p3.y - PS1.y) + (PSH1.y - p4.y);
        float ax, ay; un2(A[rr], ax, ay);
        float vx = fmaf(-cc, bxv, ax);
        float vy = fmaf(-cc, byv, ay);
        sq = fmaf(vx, vx, sq);
        sq = fmaf(vy, vy, sq);
    }
#pragma unroll
    for (int o = 16; o > 0; o >>= 1) sq += __shfl_xor_sync(0xffffffffu, sq, o);
    if ((tid & 31) == 0) sred[tid >> 5] = sq;
    __syncthreads();
    if (tid == 0)
        atomicAdd(&g_acc[s], (double)(sred[0] + sred[1] + sred[2] + sred[3]));
}

// Fat vpass: all sigmas, descending K; per sigma 768 blocks = (2, 32, 12).
__global__ void __launch_bounds__(128, 4) vpass_all() {
    __shared__ alignas(16) u64 smbuf[2 * MAXK + 4];
    int b = blockIdx.x;
    int s = b / 768;
    int id = b - s * 768;
    int bx = id & 1;
    int by = (id >> 1) & 31;
    int bz = id >> 6;
    switch (s) {
        case 0: vpass_body<155>(5, bx, by, bz, smbuf); break;
        case 1: vpass_body<77> (4, bx, by, bz, smbuf); break;
        case 2: vpass_body<39> (3, bx, by, bz, smbuf); break;
        case 3: vpass_body<21> (2, bx, by, bz, smbuf); break;
        case 4: vpass_body<11> (1, bx, by, bz, smbuf); break;
        default:vpass_body<5>  (0, bx, by, bz, smbuf); break;
    }
}

// ---------------------------------------------------------------------------
__global__ void fin_kernel(float* out) {
    double L = 0.0;
    for (int s = 0; s < NSIG; s++) L += (double)c_w[s] * g_acc[s];
    out[0] = (float)(L / (double)NPIX);
}

// ---------------------------------------------------------------------------
extern "C" void kernel_launch(void* const* d_in, const int* in_sizes, int n_in,
                              void* d_out, int out_size) {
    const float* input  = (const float*)d_in[0];
    const float* target = (const float*)d_in[1];

    init_kernel<<<NSIG, 160>>>();
    diff_kernel<<<(NPIX / 4 + 255) / 256, 256>>>(input, target);
    hpass_all<<<NSIG * 1536, 128>>>();
    sprefix_all<<<NSIG * NC * 8, 512>>>();
    vpass_all<<<NSIG * 768, 128>>>();
    fin_kernel<<<1, 1>>>((float*)d_out);
}

// round 13
// speedup vs baseline: 1.6993x; 1.0287x over previous
#include <cuda_runtime.h>
#include <math.h>

#define HH 512
#define WW 512
#define W2C 256
#define NC 12
#define NPIX (NC*HH*WW)
#define NSIG 6
#define MAXK 155
#define DPI 3.14159265358979323846

typedef unsigned long long u64;

__device__ ulonglong2 g_UV[NSIG][NPIX / 2];          // {U-pair, V-pair} per column-pair
__device__ float g_S[NSIG][NPIX];
__device__ float2 g_PS[2][NC * (HH + 1) * W2C];      // column prefix of S for s=4,5 only
__device__ u64   g_E2[NSIG][MAXK];
__device__ u64   g_H2[NSIG][MAXK];
__device__ float g_cc[NSIG];
__device__ double g_acc[NSIG];

__constant__ int    c_k[NSIG]   = {5, 11, 21, 39, 77, 155};
__constant__ double c_sig[NSIG] = {0.6, 1.2, 2.4, 4.8, 9.6, 19.2};
__constant__ float  c_w[NSIG]   = {600.f, 500.f, 400.f, 20.f, 10.f, 10.f};

__device__ __forceinline__ u64 pk2(float lo, float hi) {
    u64 r; asm("mov.b64 %0,{%1,%2};" : "=l"(r) : "f"(lo), "f"(hi)); return r;
}
__device__ __forceinline__ void un2(u64 v, float& lo, float& hi) {
    asm("mov.b64 {%0,%1},%2;" : "=f"(lo), "=f"(hi) : "l"(v));
}
__device__ __forceinline__ u64 fma2(u64 a, u64 b, u64 c) {
    u64 d; asm("fma.rn.f32x2 %0,%1,%2,%3;" : "=l"(d) : "l"(a), "l"(b), "l"(c)); return d;
}

// ---------------------------------------------------------------------------
__global__ void init_kernel() {
    int s = blockIdx.x;
    int k = c_k[s];
    double ss = c_sig[s] * c_sig[s];
    int t = threadIdx.x;
    if (t == 0) g_acc[s] = 0.0;
    if (t < k) {
        double x = (double)t - (double)(k - 1) * 0.5;
        double e = exp(-(x * x) / (2.0 * ss));
        double h = (x * x - ss) * e / (2.0 * DPI * ss * ss);
        g_E2[s][t] = pk2((float)e, (float)e);
        g_H2[s][t] = pk2((float)h, (float)h);
    }
    __syncthreads();
    if (t == 0) {
        double sg = 0.0, sh = 0.0;
        for (int i = 0; i < k; i++) {
            float e, e1, h, h1;
            un2(g_E2[s][i], e, e1);
            un2(g_H2[s][i], h, h1);
            sg += (double)e; sh += (double)h;
        }
        g_cc[s] = (float)(2.0 * sg * sh / ((double)k * (double)k));
    }
}

// ---------------------------------------------------------------------------
// hpass body: diff fused at staging; horizontal convs (E, h) + box via prefix.
// Row-pair packed f32x2. Writes interleaved UV + S, per sigma.
// ---------------------------------------------------------------------------
template<int K>
__device__ __forceinline__ void hpass_body(int s, int bx, u64* smbuf,
                                           const float* __restrict__ a,
                                           const float* __restrict__ b) {
    constexpr int P = K / 2;
    constexpr int XW = WW + 2 * P;
    constexpr int SST = (XW + 7) / 8 + 1;
    u64* spad0 = smbuf;                 // [2][8*SST]
    u64* sE = smbuf + 2 * 8 * SST;      // [K]
    u64* sH = sE + K;                   // [K]
    int tid = threadIdx.x;
    for (int i = tid; i < K; i += 128) { sE[i] = g_E2[s][i]; sH[i] = g_H2[s][i]; }
    int r0 = bx * 4;
    for (int idx = tid; idx < 2 * XW; idx += 128) {
        int pr = (idx >= XW) ? 1 : 0;
        int x = idx - pr * XW;
        int c = x - P;
        c = c < 0 ? -c : c;
        c = c >= WW ? 2 * WW - 2 - c : c;
        size_t off = (size_t)(r0 + 2 * pr) * WW + c;
        float d0 = a[off] - b[off];
        float d1 = a[off + WW] - b[off + WW];
        spad0[pr * 8 * SST + (x & 7) * SST + (x >> 3)] = pk2(d0, d1);
    }
    __syncthreads();

    int tx = tid & 63;
    const u64* sp = spad0 + (tid >> 6) * 8 * SST;
    u64 w[8], AE[8], AH[8];
    float2 Sa[8];
    float Px = 0.f, Py = 0.f;
#pragma unroll
    for (int i = 0; i < 8; i++) { AE[i] = 0ull; AH[i] = 0ull; }

#pragma unroll
    for (int t = 0; t < 8; ++t) {
        u64 v = sp[t * SST + tx];
        w[t] = v;
        Sa[t].x = -Px; Sa[t].y = -Py;
        float vx, vy; un2(v, vx, vy);
        Px += vx; Py += vy;
        if (t >= K - 1) { Sa[t - K + 1].x += Px; Sa[t - K + 1].y += Py; }
    }

    constexpr int MA = (K > 9) ? ((K - 9) / 8) * 8 : 0;
    for (int m = 0; m < MA / 8; ++m) {
#pragma unroll
        for (int jj = 0; jj < 8; ++jj) {
            int d = m * 8 + jj;
            u64 e2 = sE[d], h2 = sH[d];
#pragma unroll
            for (int rr = 0; rr < 8; ++rr) {
                u64 v = w[(jj + rr) & 7];
                AE[rr] = fma2(e2, v, AE[rr]);
                AH[rr] = fma2(h2, v, AH[rr]);
            }
            u64 nv = sp[jj * SST + tx + m + 1];
            w[jj] = nv;
            float vx, vy; un2(nv, vx, vy);
            Px += vx; Py += vy;
        }
    }
#pragma unroll
    for (int e = 0; e < K - MA; ++e) {
        const int d = MA + e;
        u64 e2 = sE[d], h2 = sH[d];
#pragma unroll
        for (int rr = 0; rr < 8; ++rr) {
            u64 v = w[(d + rr) & 7];
            AE[rr] = fma2(e2, v, AE[rr]);
            AH[rr] = fma2(h2, v, AH[rr]);
        }
        if (d <= K - 2) {
            u64 nv = sp[(d & 7) * SST + tx + ((d + 8) >> 3)];
            w[d & 7] = nv;
            float vx, vy; un2(nv, vx, vy);
            Px += vx; Py += vy;
            if (d >= K - 9) { Sa[d + 9 - K].x += Px; Sa[d + 9 - K].y += Py; }
        }
    }

    // unpack rows
    float eA[8], eB[8], hA[8], hB[8];
#pragma unroll
    for (int rr = 0; rr < 8; ++rr) un2(AE[rr], eA[rr], eB[rr]);
#pragma unroll
    for (int rr = 0; rr < 8; ++rr) un2(AH[rr], hA[rr], hB[rr]);

    int rA = r0 + 2 * (tid >> 6);       // first row of this pair
    int j0 = tx * 8;                    // first column
    int c2 = j0 >> 1;                   // first column-pair index

    // interleaved UV stores: float4 = {U[2c],U[2c+1],V[2c],V[2c+1]}
    float4* UVb = (float4*)g_UV[s];
    size_t uvA = (size_t)rA * W2C + c2;
    size_t uvB = uvA + W2C;
#pragma unroll
    for (int i = 0; i < 4; ++i)
        UVb[uvA + i] = make_float4(eA[2*i], eA[2*i+1], hA[2*i], hA[2*i+1]);
#pragma unroll
    for (int i = 0; i < 4; ++i)
        UVb[uvB + i] = make_float4(eB[2*i], eB[2*i+1], hB[2*i], hB[2*i+1]);

    // S stores
    float* Sb = g_S[s];
    size_t rbase = (size_t)rA * WW + j0;
    float la[8], lb[8];
#pragma unroll
    for (int rr = 0; rr < 8; ++rr) { la[rr] = Sa[rr].x; lb[rr] = Sa[rr].y; }
    *(float4*)(Sb + rbase)          = make_float4(la[0], la[1], la[2], la[3]);
    *(float4*)(Sb + rbase + 4)      = make_float4(la[4], la[5], la[6], la[7]);
    *(float4*)(Sb + rbase + WW)     = make_float4(lb[0], lb[1], lb[2], lb[3]);
    *(float4*)(Sb + rbase + WW + 4) = make_float4(lb[4], lb[5], lb[6], lb[7]);
}

// Fat hpass: all sigmas in one launch, descending K for load balance.
__global__ void __launch_bounds__(128, 4) hpass_all(const float* __restrict__ a,
                                                    const float* __restrict__ b) {
    __shared__ alignas(16) u64 smbuf[1672];
    int bb = blockIdx.x;
    int s = bb / 1536;          // 0..5 in launch order
    int bx = bb - s * 1536;
    switch (s) {
        case 0: hpass_body<155>(5, bx, smbuf, a, b); break;
        case 1: hpass_body<77> (4, bx, smbuf, a, b); break;
        case 2: hpass_body<39> (3, bx, smbuf, a, b); break;
        case 3: hpass_body<21> (2, bx, smbuf, a, b); break;
        case 4: hpass_body<11> (1, bx, smbuf, a, b); break;
        default:hpass_body<5>  (0, bx, smbuf, a, b); break;
    }
}

// ---------------------------------------------------------------------------
// Segmented column prefix of S for s = 4, 5 only: PS[r] = sum of rows [0, r).
// Grid: 2*NC*8 chunks; block = 512 threads = 16 segments x 32 column-pairs.
// ---------------------------------------------------------------------------
__global__ void __launch_bounds__(512, 2) sprefix2() {
    __shared__ float2 ssum[16][32];
    int b = blockIdx.x;                 // 2 * NC * 8
    int sp = b / (NC * 8);              // 0,1 -> sigma 4+sp
    int rem = b - sp * (NC * 8);
    int img = rem >> 3;
    int chunk = rem & 7;
    int tid = threadIdx.x;
    int c = tid & 31;
    int seg = tid >> 5;                 // 0..15
    int col2 = chunk * 32 + c;
    const float2* Sq = (const float2*)g_S[4 + sp] + (size_t)img * HH * W2C + col2;
    float2* PS = g_PS[sp] + (size_t)img * (HH + 1) * W2C + col2;

    int r0 = seg * 32;
    float2 acc = make_float2(0.f, 0.f);
    for (int i = 0; i < 32; ++i) {
        float2 v = Sq[(size_t)(r0 + i) * W2C];
        acc.x += v.x; acc.y += v.y;
    }
    ssum[seg][c] = acc;
    __syncthreads();
    float2 off = make_float2(0.f, 0.f);
    for (int s2 = 0; s2 < 16; ++s2) {
        if (s2 < seg) { off.x += ssum[s2][c].x; off.y += ssum[s2][c].y; }
    }
    for (int i = 0; i < 32; ++i) {
        PS[(size_t)(r0 + i) * W2C] = off;
        float2 v = Sq[(size_t)(r0 + i) * W2C];
        off.x += v.x; off.y += v.y;
    }
    if (seg == 15) PS[(size_t)HH * W2C] = off;
}

// ---------------------------------------------------------------------------
// vpass (PS variant, large K): box via integral image.
// ---------------------------------------------------------------------------
template<int K>
__device__ __forceinline__ void vpassPS(int s, int psidx, int bx, int by, int bz, u64* smbuf) {
    constexpr int P = K / 2;
    u64* sE = smbuf;
    u64* sH = sE + K;
    float* sred = (float*)(sH + K);
    int tid = threadIdx.x;
    for (int i = tid; i < K; i += 128) { sE[i] = g_E2[s][i]; sH[i] = g_H2[s][i]; }
    __syncthreads();

    int col2 = bx * 128 + tid;
    int i0 = by * 16;
    size_t ib = (size_t)bz * (HH * W2C);
    const ulonglong2* __restrict__ UVq = (const ulonglong2*)g_UV[s] + ib;

    u64 wu[16], wv[16], A[16];
#pragma unroll
    for (int i = 0; i < 16; i++) A[i] = 0ull;
    int base = i0 - P;

#pragma unroll
    for (int t = 0; t < 16; ++t) {
        int r = base + t; r = r < 0 ? -r : r; r = r >= HH ? 2 * HH - 2 - r : r;
        ulonglong2 q = UVq[(size_t)r * W2C + col2];
        wu[t] = q.x; wv[t] = q.y;
    }

    constexpr int MA = (K > 17) ? ((K - 17) / 16) * 16 : 0;
    for (int m = 0; m < MA / 16; ++m) {
#pragma unroll
        for (int jj = 0; jj < 16; ++jj) {
            int d = m * 16 + jj;
            u64 e2 = sE[d], h2 = sH[d];
#pragma unroll
            for (int rr = 0; rr < 16; ++rr) {
                A[rr] = fma2(h2, wu[(jj + rr) & 15], A[rr]);
                A[rr] = fma2(e2, wv[(jj + rr) & 15], A[rr]);
            }
            int r = base + d + 16; r = r < 0 ? -r : r; r = r >= HH ? 2 * HH - 2 - r : r;
            ulonglong2 q = UVq[(size_t)r * W2C + col2];
            wu[jj] = q.x; wv[jj] = q.y;
        }
    }
#pragma unroll
    for (int e = 0; e < K - MA; ++e) {
        const int d = MA + e;
        u64 e2 = sE[d], h2 = sH[d];
#pragma unroll
        for (int rr = 0; rr < 16; ++rr) {
            A[rr] = fma2(h2, wu[(d + rr) & 15], A[rr]);
            A[rr] = fma2(e2, wv[(d + rr) & 15], A[rr]);
        }
        if (d <= K - 2) {
            int r = base + d + 16; r = r < 0 ? -r : r; r = r >= HH ? 2 * HH - 2 - r : r;
            ulonglong2 q = UVq[(size_t)r * W2C + col2];
            wu[d & 15] = q.x; wv[d & 15] = q.y;
        }
    }

    const float2* __restrict__ PSp = g_PS[psidx] + (size_t)bz * (HH + 1) * W2C;
    float2 PS1  = PSp[(size_t)1 * W2C + col2];
    float2 PSH1 = PSp[(size_t)(HH - 1) * W2C + col2];
    float cc = g_cc[s];
    float sq = 0.f;
#pragma unroll
    for (int rr = 0; rr < 16; ++rr) {
        int o = i0 + rr;
        int aa = o - P, bb = o + P;
        int i1 = bb + 1 < HH ? bb + 1 : HH;
        int i2 = aa > 0 ? aa : 0;
        int i3 = 1 - aa > 1 ? 1 - aa : 1;
        int i4t = 2 * HH - 2 - bb;
        int i4 = i4t < HH - 1 ? i4t : HH - 1;
        float2 p1 = PSp[(size_t)i1 * W2C + col2];
        float2 p2 = PSp[(size_t)i2 * W2C + col2];
        float2 p3 = PSp[(size_t)i3 * W2C + col2];
        float2 p4 = PSp[(size_t)i4 * W2C + col2];
        float bxv = (p1.x - p2.x) + (p3.x - PS1.x) + (PSH1.x - p4.x);
        float byv = (p1.y - p2.y) + (p3.y - PS1.y) + (PSH1.y - p4.y);
        float ax, ay; un2(A[rr], ax, ay);
        float vx = fmaf(-cc, bxv, ax);
        float vy = fmaf(-cc, byv, ay);
        sq = fmaf(vx, vx, sq);
        sq = fmaf(vy, vy, sq);
    }
#pragma unroll
    for (int o = 16; o > 0; o >>= 1) sq += __shfl_xor_sync(0xffffffffu, sq, o);
    if ((tid & 31) == 0) sred[tid >> 5] = sq;
    __syncthreads();
    if (tid == 0)
        atomicAdd(&g_acc[s], (double)(sred[0] + sred[1] + sred[2] + sred[3]));
}

// ---------------------------------------------------------------------------
// vpass (inline-prefix variant, small K): box via running register prefix.
// ---------------------------------------------------------------------------
template<int K>
__device__ __forceinline__ void vpassIN(int s, int bx, int by, int bz, u64* smbuf) {
    constexpr int P = K / 2;
    u64* sE = smbuf;
    u64* sH = sE + K;
    float* sred = (float*)(sH + K);
    int tid = threadIdx.x;
    for (int i = tid; i < K; i += 128) { sE[i] = g_E2[s][i]; sH[i] = g_H2[s][i]; }
    __syncthreads();

    int col2 = bx * 128 + tid;
    int i0 = by * 16;
    size_t ib = (size_t)bz * (HH * W2C);
    const ulonglong2* __restrict__ UVq = (const ulonglong2*)g_UV[s] + ib;
    const float2* __restrict__ Sq = (const float2*)g_S[s] + ib;

    u64 wu[16], wv[16], A[16];
    float2 Sa[16];
    float Px = 0.f, Py = 0.f;
#pragma unroll
    for (int i = 0; i < 16; i++) A[i] = 0ull;
    int base = i0 - P;

#pragma unroll
    for (int t = 0; t < 16; ++t) {
        int r = base + t; r = r < 0 ? -r : r; r = r >= HH ? 2 * HH - 2 - r : r;
        int off = r * W2C + col2;
        ulonglong2 q = UVq[off];
        wu[t] = q.x; wv[t] = q.y;
        float2 sv = Sq[off];
        Sa[t].x = -Px; Sa[t].y = -Py;
        Px += sv.x; Py += sv.y;
        if (t >= K - 1) { Sa[t - K + 1].x += Px; Sa[t - K + 1].y += Py; }
    }

    constexpr int MA = (K > 17) ? ((K - 17) / 16) * 16 : 0;
    for (int m = 0; m < MA / 16; ++m) {
#pragma unroll
        for (int jj = 0; jj < 16; ++jj) {
            int d = m * 16 + jj;
            u64 e2 = sE[d], h2 = sH[d];
#pragma unroll
            for (int rr = 0; rr < 16; ++rr) {
                A[rr] = fma2(h2, wu[(jj + rr) & 15], A[rr]);
                A[rr] = fma2(e2, wv[(jj + rr) & 15], A[rr]);
            }
            int r = base + d + 16; r = r < 0 ? -r : r; r = r >= HH ? 2 * HH - 2 - r : r;
            int off = r * W2C + col2;
            ulonglong2 q = UVq[off];
            wu[jj] = q.x; wv[jj] = q.y;
            float2 sv = Sq[off];
            Px += sv.x; Py += sv.y;
        }
    }
#pragma unroll
    for (int e = 0; e < K - MA; ++e) {
        const int d = MA + e;
        u64 e2 = sE[d], h2 = sH[d];
#pragma unroll
        for (int rr = 0; rr < 16; ++rr) {
            A[rr] = fma2(h2, wu[(d + rr) & 15], A[rr]);
            A[rr] = fma2(e2, wv[(d + rr) & 15], A[rr]);
        }
        if (d <= K - 2) {
            int r = base + d + 16; r = r < 0 ? -r : r; r = r >= HH ? 2 * HH - 2 - r : r;
            int off = r * W2C + col2;
            ulonglong2 q = UVq[off];
            wu[d & 15] = q.x; wv[d & 15] = q.y;
            float2 sv = Sq[off];
            Px += sv.x; Py += sv.y;
            if (d >= K - 17) { Sa[d + 17 - K].x += Px; Sa[d + 17 - K].y += Py; }
        }
    }

    float cc = g_cc[s];
    float sq = 0.f;
#pragma unroll
    for (int rr = 0; rr < 16; ++rr) {
        float ax, ay; un2(A[rr], ax, ay);
        float vx = fmaf(-cc, Sa[rr].x, ax);
        float vy = fmaf(-cc, Sa[rr].y, ay);
        sq = fmaf(vx, vx, sq);
        sq = fmaf(vy, vy, sq);
    }
#pragma unroll
    for (int o = 16; o > 0; o >>= 1) sq += __shfl_xor_sync(0xffffffffu, sq, o);
    if ((tid & 31) == 0) sred[tid >> 5] = sq;
    __syncthreads();
    if (tid == 0)
        atomicAdd(&g_acc[s], (double)(sred[0] + sred[1] + sred[2] + sred[3]));
}

// Fat vpass: all sigmas, descending K; PS path for K=155,77; inline for the rest.
__global__ void __launch_bounds__(128, 3) vpass_all() {
    __shared__ alignas(16) u64 smbuf[2 * MAXK + 4];
    int b = blockIdx.x;
    int s = b / 768;
    int id = b - s * 768;
    int bx = id & 1;
    int by = (id >> 1) & 31;
    int bz = id >> 6;
    switch (s) {
        case 0: vpassPS<155>(5, 1, bx, by, bz, smbuf); break;
        case 1: vpassPS<77> (4, 0, bx, by, bz, smbuf); break;
        case 2: vpassIN<39> (3, bx, by, bz, smbuf); break;
        case 3: vpassIN<21> (2, bx, by, bz, smbuf); break;
        case 4: vpassIN<11> (1, bx, by, bz, smbuf); break;
        default:vpassIN<5>  (0, bx, by, bz, smbuf); break;
    }
}

// ---------------------------------------------------------------------------
__global__ void fin_kernel(float* out) {
    double L = 0.0;
    for (int s = 0; s < NSIG; s++) L += (double)c_w[s] * g_acc[s];
    out[0] = (float)(L / (double)NPIX);
}

// ---------------------------------------------------------------------------
extern "C" void kernel_launch(void* const* d_in, const int* in_sizes, int n_in,
                              void* d_out, int out_size) {
    const float* input  = (const float*)d_in[0];
    const float* target = (const float*)d_in[1];

    init_kernel<<<NSIG, 160>>>();
    hpass_all<<<NSIG * 1536, 128>>>(input, target);
    sprefix2<<<2 * NC * 8, 512>>>();
    vpass_all<<<NSIG * 768, 128>>>();
    fin_kernel<<<1, 1>>>((float*)d_out);
}